// round 15
// baseline (speedup 1.0000x reference)
#include <cuda_runtime.h>
#include <math.h>

// ---------------------------------------------------------------------------
// GCN(2)->node0->LSTM->FC. Only the 2-hop in-neighborhood of node 0 matters:
// S1 = in-neighbors of 0 (~32).
// KEY ALGEBRA: layer-1 aggregation is linear in W1, so accumulate weighted
// RAW x-columns per S1 node first (xacc[j] = sum_e w_e * x[:,src_e]), then
// apply W1 once per S1 node in the tail:  acc1[j] = xacc[j] @ W1.
// FIVE kernels, TWO edge passes, no standalone hlin, no W1 in the hot path:
//   1 init     : zero deg/flags/bm1/xacc, seed node 0
//   2 scan1deg : full in-degree histogram + dst==0 -> e0 list, S1 set, bm1
//   3 scan2    : dst in bm1 (SMEM) -> e1 edge list only
//   4 xagg     : per task (self-loop or e1 edge): gather x[:,src] (128
//                lanes), scale by GCN norm, atomicAdd into xacc[dp].
//                No smem, no syncs, no W1.
//   5 tail     : one block: acc1 = xacc@W1 (+b1, relu) ; h2 = @W2 ;
//                node-0 layer-2 agg ; LSTM ; FC -> out
// ---------------------------------------------------------------------------

#define NN_MAX   100000
#define IND      128
#define H        64
#define S1CAP    512
#define E0CAP    2048
#define ECAP     32768
#define BMW      ((NN_MAX + 31) / 32)   // 3125 words = 12.5 KB
#define SCAN_B   296
#define SCAN_T   512

static __device__ int      g_deg[NN_MAX];     // FULL in-degree histogram
static __device__ int      g_flag1[NN_MAX];   // pos+1 in S1 (0 = not member)
static __device__ unsigned g_bm1[BMW];
static __device__ int      g_s1[S1CAP];
static __device__ int      g_e0[E0CAP];       // src of edges with dst==0
static __device__ int2     g_e1[ECAP];        // edges with dst in S1
static __device__ int      g_cnt1, g_cntE0, g_cntE1;
static __device__ float    g_xacc[S1CAP][IND]; // weighted x-column sums
static __device__ float    g_h1[S1CAP][H];
static __device__ float    g_h2[S1CAP][H];

// ---------------------------------------------------------------------------
__global__ void k_init(int N) {
    int i = blockIdx.x * blockDim.x + threadIdx.x;
    int nth = gridDim.x * blockDim.x;
    for (int k = i; k < N; k += nth) { g_deg[k] = 0; g_flag1[k] = 0; }
    for (int k = i; k < BMW; k += nth) g_bm1[k] = 0u;
    for (int k = i; k < S1CAP * IND; k += nth) ((float*)g_xacc)[k] = 0.0f;
    if (i == 0) {
        g_cnt1 = 1; g_cntE0 = 0; g_cntE1 = 0;
        g_s1[0] = 0;
        g_flag1[0] = 1;
        g_bm1[0] = 1u;
    }
}

// ---------------------------------------------------------------------------
// scan1 + degree histogram fused: every edge bumps deg[dst]; dst==0 edges
// additionally build e0 / S1 / bm1.
__device__ __forceinline__ void s1d_one(const int* __restrict__ src, int d, int idx) {
    atomicAdd(&g_deg[d], 1);
    if (d == 0) {
        int s = __ldcg(&src[idx]);
        int p = atomicAdd(&g_cntE0, 1);
        if (p < E0CAP) g_e0[p] = s;
        if (atomicCAS(&g_flag1[s], 0, -1) == 0) {
            int q = atomicAdd(&g_cnt1, 1);
            if (q < S1CAP) g_s1[q] = s;
            g_flag1[s] = q + 1;
            atomicOr(&g_bm1[s >> 5], 1u << (s & 31));
        }
    }
}

__global__ void __launch_bounds__(SCAN_T)
k_scan1deg(const int* __restrict__ src, const int* __restrict__ dst, int E) {
    int gid = blockIdx.x * SCAN_T + threadIdx.x;
    int nth = SCAN_B * SCAN_T;
    int E4 = E >> 2;
    const int4* d4 = (const int4*)dst;
    int i = gid;
    for (; i + 3 * nth < E4; i += 4 * nth) {
        int4 v0 = __ldcg(&d4[i]);
        int4 v1 = __ldcg(&d4[i + nth]);
        int4 v2 = __ldcg(&d4[i + 2 * nth]);
        int4 v3 = __ldcg(&d4[i + 3 * nth]);
        int j;
        j = i;           s1d_one(src, v0.x, 4*j); s1d_one(src, v0.y, 4*j+1); s1d_one(src, v0.z, 4*j+2); s1d_one(src, v0.w, 4*j+3);
        j = i + nth;     s1d_one(src, v1.x, 4*j); s1d_one(src, v1.y, 4*j+1); s1d_one(src, v1.z, 4*j+2); s1d_one(src, v1.w, 4*j+3);
        j = i + 2 * nth; s1d_one(src, v2.x, 4*j); s1d_one(src, v2.y, 4*j+1); s1d_one(src, v2.z, 4*j+2); s1d_one(src, v2.w, 4*j+3);
        j = i + 3 * nth; s1d_one(src, v3.x, 4*j); s1d_one(src, v3.y, 4*j+1); s1d_one(src, v3.z, 4*j+2); s1d_one(src, v3.w, 4*j+3);
    }
    for (; i < E4; i += nth) {
        int4 v = __ldcg(&d4[i]);
        s1d_one(src, v.x, 4*i); s1d_one(src, v.y, 4*i+1); s1d_one(src, v.z, 4*i+2); s1d_one(src, v.w, 4*i+3);
    }
    for (int j = (E4 << 2) + gid; j < E; j += nth) s1d_one(src, __ldcg(&dst[j]), j);
}

// ---------------------------------------------------------------------------
// scan2: dst in bm1 (SMEM) -> append (src,dst) to e1. Nothing else.
__device__ __forceinline__ void s2_one(const unsigned* sbm,
                                       const int* __restrict__ src, int d, int idx) {
    if ((sbm[d >> 5] >> (d & 31)) & 1u) {
        int s = __ldcg(&src[idx]);
        int p = atomicAdd(&g_cntE1, 1);
        if (p < ECAP) g_e1[p] = make_int2(s, d);
    }
}

__global__ void __launch_bounds__(SCAN_T)
k_scan2(const int* __restrict__ src, const int* __restrict__ dst, int E) {
    __shared__ unsigned sbm[BMW];
    for (int k = threadIdx.x; k < BMW; k += SCAN_T) sbm[k] = __ldg(&g_bm1[k]);
    __syncthreads();
    int gid = blockIdx.x * SCAN_T + threadIdx.x;
    int nth = SCAN_B * SCAN_T;
    int E4 = E >> 2;
    const int4* d4 = (const int4*)dst;
    int i = gid;
    for (; i + 3 * nth < E4; i += 4 * nth) {
        int4 v0 = __ldcg(&d4[i]);
        int4 v1 = __ldcg(&d4[i + nth]);
        int4 v2 = __ldcg(&d4[i + 2 * nth]);
        int4 v3 = __ldcg(&d4[i + 3 * nth]);
        int j;
        j = i;           s2_one(sbm, src, v0.x, 4*j); s2_one(sbm, src, v0.y, 4*j+1); s2_one(sbm, src, v0.z, 4*j+2); s2_one(sbm, src, v0.w, 4*j+3);
        j = i + nth;     s2_one(sbm, src, v1.x, 4*j); s2_one(sbm, src, v1.y, 4*j+1); s2_one(sbm, src, v1.z, 4*j+2); s2_one(sbm, src, v1.w, 4*j+3);
        j = i + 2 * nth; s2_one(sbm, src, v2.x, 4*j); s2_one(sbm, src, v2.y, 4*j+1); s2_one(sbm, src, v2.z, 4*j+2); s2_one(sbm, src, v2.w, 4*j+3);
        j = i + 3 * nth; s2_one(sbm, src, v3.x, 4*j); s2_one(sbm, src, v3.y, 4*j+1); s2_one(sbm, src, v3.z, 4*j+2); s2_one(sbm, src, v3.w, 4*j+3);
    }
    for (; i < E4; i += nth) {
        int4 v = __ldcg(&d4[i]);
        s2_one(sbm, src, v.x, 4*i); s2_one(sbm, src, v.y, 4*i+1); s2_one(sbm, src, v.z, 4*i+2); s2_one(sbm, src, v.w, 4*i+3);
    }
    for (int j = (E4 << 2) + gid; j < E; j += nth) {
        int d = __ldcg(&dst[j]);
        s2_one(sbm, src, d, j);
    }
}

// ---------------------------------------------------------------------------
// xagg: tasks = [m1 self-loops | mE edges]. Each 128-thread group handles
// one task: lane lt reads x[lt*N + u], scales by the GCN norm, atomicAdds
// into xacc[dp][lt]. No shared memory, no syncs, fully independent groups.
__global__ void __launch_bounds__(512)
k_xagg(const float* __restrict__ x, int N) {
    int lt = threadIdx.x & 127;
    int group = blockIdx.x * 4 + (threadIdx.x >> 7);
    int ngroups = gridDim.x * 4;
    int m1 = g_cnt1; if (m1 > S1CAP) m1 = S1CAP;
    int mE = g_cntE1; if (mE > ECAP) mE = ECAP;
    int total = m1 + mE;
    for (int t = group; t < total; t += ngroups) {
        int u, dp;
        float w;
        if (t < m1) {
            u  = __ldg(&g_s1[t]);
            dp = t;
            float di = rsqrtf((float)__ldg(&g_deg[u]) + 1.0f);
            w = di * di;
        } else {
            int2 ed = __ldg(&g_e1[t - m1]);
            u  = ed.x;
            dp = __ldg(&g_flag1[ed.y]) - 1;
            w = rsqrtf((float)__ldg(&g_deg[ed.x]) + 1.0f)
              * rsqrtf((float)__ldg(&g_deg[ed.y]) + 1.0f);
        }
        float v = __ldg(&x[(size_t)lt * N + u]);
        atomicAdd(&g_xacc[dp][lt], w * v);
    }
}

// ---------------------------------------------------------------------------
// Tail: acc1 = xacc @ W1 (+b1, relu) -> h1 ; h2 = h1 @ W2 ; node-0 layer-2
// aggregation ; LSTM single step ; FC -> out. W1 and W2 share one smem
// buffer (W1 loaded first, W2 overwrites it after phase A).
__global__ void __launch_bounds__(512)
k_tail(const float* __restrict__ W1, const float* __restrict__ b1,
       const float* __restrict__ W2, const float* __restrict__ b2,
       const float* __restrict__ w_ih,
       const float* __restrict__ b_ih, const float* __restrict__ b_hh,
       const float* __restrict__ fc_w, const float* __restrict__ fc_b,
       float* __restrict__ out) {
    __shared__ float sW[IND * H];       // 32 KB: W1 in phase A, W2 in phase B
    __shared__ float z[H], gates[4 * H], red[H];
    __shared__ float scof[256];
    __shared__ int   sspb[256];

    int tid = threadIdx.x;
    int m1 = g_cnt1; if (m1 > S1CAP) m1 = S1CAP;

    // ---- phase A: h1 = relu(xacc @ W1 + b1) ----
    for (int k = tid; k < IND * H; k += 512) sW[k] = W1[k];
    __syncthreads();
    for (int t = tid; t < m1 * H; t += 512) {
        int j = t >> 6, o = t & 63;
        float acc = 0.0f;
        #pragma unroll 16
        for (int d = 0; d < IND; d++) acc += g_xacc[j][d] * sW[d * H + o];
        g_h1[j][o] = fmaxf(acc + b1[o], 0.0f);
    }
    __syncthreads();

    // ---- phase B: h2 = h1 @ W2 ----
    for (int k = tid; k < H * H; k += 512) sW[k] = W2[k];
    __syncthreads();
    for (int t = tid; t < m1 * H; t += 512) {
        int j = t >> 6, o = t & 63;
        float acc = 0.0f;
        #pragma unroll
        for (int h = 0; h < H; h++) acc += g_h1[j][h] * sW[h * H + o];
        g_h2[j][o] = acc;
    }
    __syncthreads();

    // ---- node-0 layer-2 aggregation ----
    int m0 = g_cntE0; if (m0 > E0CAP) m0 = E0CAP;
    float d0 = rsqrtf((float)g_deg[0] + 1.0f);
    float zv = 0.0f;
    if (tid < H) zv = b2[tid] + d0 * d0 * g_h2[0][tid];
    for (int base = 0; base < m0; base += 256) {
        int k = base + tid;
        if (tid < 256 && k < m0) {
            int s = g_e0[k];
            scof[tid] = rsqrtf((float)g_deg[s] + 1.0f) * d0;
            sspb[tid] = g_flag1[s] - 1;
        }
        __syncthreads();
        int lim = m0 - base; if (lim > 256) lim = 256;
        if (tid < H)
            for (int e = 0; e < lim; e++) zv += scof[e] * g_h2[sspb[e]][tid];
        __syncthreads();
    }
    if (tid < H) z[tid] = zv;
    __syncthreads();

    // ---- LSTM single step (h0 = c0 = 0) + FC ----
    if (tid < 4 * H) {
        float a = b_ih[tid] + b_hh[tid];
        #pragma unroll
        for (int h = 0; h < H; h++) a += __ldg(&w_ih[tid * H + h]) * z[h];
        gates[tid] = a;
    }
    __syncthreads();
    if (tid < H) {
        float ig = gates[tid];
        float gg = gates[2 * H + tid];
        float og = gates[3 * H + tid];
        float si = 1.0f / (1.0f + expf(-ig));
        float c  = si * tanhf(gg);
        float so = 1.0f / (1.0f + expf(-og));
        float hy = so * tanhf(c);
        red[tid] = hy * fc_w[tid];
    }
    __syncthreads();
    if (tid == 0) {
        float s = 0.0f;
        for (int k = 0; k < H; k++) s += red[k];
        out[0] = s + fc_b[0];
    }
}

// ---------------------------------------------------------------------------
extern "C" void kernel_launch(void* const* d_in, const int* in_sizes, int n_in,
                              void* d_out, int out_size) {
    const float* x    = (const float*)d_in[0];
    const int*   ei   = (const int*)d_in[1];
    const float* W1   = (const float*)d_in[2];
    const float* b1   = (const float*)d_in[3];
    const float* W2   = (const float*)d_in[4];
    const float* b2   = (const float*)d_in[5];
    const float* w_ih = (const float*)d_in[6];
    // d_in[7] = w_hh (unused: h0 = c0 = 0)
    const float* b_ih = (const float*)d_in[8];
    const float* b_hh = (const float*)d_in[9];
    const float* fc_w = (const float*)d_in[10];
    const float* fc_b = (const float*)d_in[11];
    float* out = (float*)d_out;

    int N = in_sizes[0] / IND;
    int E = in_sizes[1] / 2;
    const int* src = ei;
    const int* dst = ei + E;

    k_init<<<200, 512>>>(N);
    k_scan1deg<<<SCAN_B, SCAN_T>>>(src, dst, E);
    k_scan2<<<SCAN_B, SCAN_T>>>(src, dst, E);
    k_xagg<<<SCAN_B, 512>>>(x, N);
    k_tail<<<1, 512>>>(W1, b1, W2, b2, w_ih, b_ih, b_hh, fc_w, fc_b, out);
}